// round 1
// baseline (speedup 1.0000x reference)
#include <cuda_runtime.h>
#include <cuda_bf16.h>

#define N_TOT   131072
#define E_DIM   128
#define QKV_DIM 384
#define OUT_DIM 768

// ---------------- device scratch (allocation-free rule: __device__ globals) ---
// table qkv: dev rows [0,10), pseudo [10,20), attr [20,120), unit [120,140)
__device__ float g_tab_qkv[140 * QKV_DIM];
__device__ float g_valA[QKV_DIM];
__device__ float g_valB[QKV_DIM];
__device__ float g_Wc[OUT_DIM * E_DIM];   // Wc[o][e] = sum_m out_w[o][m]*out_proj_w[m][e]
__device__ float g_bc[OUT_DIM];
__device__ float g_composed[(size_t)N_TOT * E_DIM];

// ---------------- P1: per-table qkv rows + value-linear A/B ------------------
// grid = 142 blocks, 384 threads. blocks 0..139 table rows; 140 -> valA; 141 -> valB
__global__ void precompute_qkv_kernel(
    const float* __restrict__ dev_t, const float* __restrict__ pse_t,
    const float* __restrict__ attr_t, const float* __restrict__ unit_t,
    const float* __restrict__ val_w, const float* __restrict__ val_b,
    const float* __restrict__ W, const float* __restrict__ b)
{
    __shared__ float emb[E_DIM];
    int blk = blockIdx.x;
    int j = threadIdx.x;  // 0..383 output dim

    const float* src;
    float* dst;
    int has_bias = 1;
    if (blk < 10)        { src = dev_t  + blk * E_DIM;         dst = g_tab_qkv + blk * QKV_DIM; }
    else if (blk < 20)   { src = pse_t  + (blk - 10) * E_DIM;  dst = g_tab_qkv + blk * QKV_DIM; }
    else if (blk < 120)  { src = attr_t + (blk - 20) * E_DIM;  dst = g_tab_qkv + blk * QKV_DIM; }
    else if (blk < 140)  { src = unit_t + (blk - 120) * E_DIM; dst = g_tab_qkv + blk * QKV_DIM; }
    else if (blk == 140) { src = val_w; dst = g_valA; has_bias = 0; }
    else                 { src = val_b; dst = g_valB; }

    if (j < E_DIM) emb[j] = src[j];
    __syncthreads();

    const float4* Wr = (const float4*)(W + (size_t)j * E_DIM);
    const float4* em = (const float4*)emb;
    float acc = has_bias ? b[j] : 0.0f;
    #pragma unroll
    for (int e4 = 0; e4 < E_DIM / 4; e4++) {
        float4 w = Wr[e4];
        float4 v = em[e4];
        acc += w.x * v.x + w.y * v.y + w.z * v.z + w.w * v.w;
    }
    dst[j] = acc;
}

// ---------------- P2: fused output projection Wc = out_w @ out_proj_w --------
// grid = 768 blocks, 128 threads
__global__ void precompute_wc_kernel(
    const float* __restrict__ out_w, const float* __restrict__ out_proj_w,
    const float* __restrict__ out_proj_b, const float* __restrict__ out_b)
{
    __shared__ float row[E_DIM];
    int o = blockIdx.x;
    int e = threadIdx.x;
    row[e] = out_w[(size_t)o * E_DIM + e];
    __syncthreads();

    float acc = 0.0f;
    #pragma unroll 8
    for (int m = 0; m < E_DIM; m++)
        acc += row[m] * out_proj_w[(size_t)m * E_DIM + e];
    g_Wc[(size_t)o * E_DIM + e] = acc;

    if (e == 0) {
        float bb = out_b[o];
        for (int m = 0; m < E_DIM; m++) bb += row[m] * out_proj_b[m];
        g_bc[o] = bb;
    }
}

// ---------------- A: attention, one warp per row -----------------------------
// per-warp smem region (floats): qkv rows 5 x stride 388 (388 % 32 == 4 ->
// conflict-free score dots), scores@1952(100), rowmax@2052(20), inv@2072(20), wk@2092(20)
#define SMW 2112
#define SC_OFF 1952
#define RM_OFF 2052
#define RS_OFF 2072
#define WK_OFF 2092

__global__ void __launch_bounds__(128) attn_kernel(
    const int* __restrict__ dev_ids, const int* __restrict__ pse_ids,
    const int* __restrict__ attr_ids, const int* __restrict__ unit_ids,
    const float* __restrict__ values, const int* __restrict__ mask,
    const float* __restrict__ inb)
{
    __shared__ float sm[4 * SMW];
    int w = threadIdx.x >> 5;
    int lane = threadIdx.x & 31;
    int n = blockIdx.x * 4 + w;
    float* S = sm + w * SMW;

    int id0 = dev_ids[n];
    int id1 = pse_ids[n];
    int id2 = attr_ids[n];
    int id4 = unit_ids[n];
    float val = values[n];
    int mk0 = mask[n * 5 + 0];
    int mk1 = mask[n * 5 + 1];
    int mk2 = mask[n * 5 + 2];
    int mk3 = mask[n * 5 + 3];
    int mk4 = mask[n * 5 + 4];

    const float4* inb4 = (const float4*)inb;
    const float4* r0 = (const float4*)(g_tab_qkv + id0 * QKV_DIM);
    const float4* r1 = (const float4*)(g_tab_qkv + (10 + id1) * QKV_DIM);
    const float4* r2 = (const float4*)(g_tab_qkv + (20 + id2) * QKV_DIM);
    const float4* r4 = (const float4*)(g_tab_qkv + (120 + id4) * QKV_DIM);

    // stage qkv rows
    {
        const float4* s0 = mk0 ? r0 : inb4;
        const float4* s1 = mk1 ? r1 : inb4;
        const float4* s2 = mk2 ? r2 : inb4;
        const float4* s4 = mk4 ? r4 : inb4;
        float4* d0 = (float4*)(S + 0 * 388);
        float4* d1 = (float4*)(S + 1 * 388);
        float4* d2 = (float4*)(S + 2 * 388);
        float4* d3 = (float4*)(S + 3 * 388);
        float4* d4 = (float4*)(S + 4 * 388);
        const float4* A4 = (const float4*)g_valA;
        const float4* B4 = (const float4*)g_valB;
        #pragma unroll
        for (int it = 0; it < 3; it++) {
            int j = lane + it * 32;  // 96 float4 per row
            d0[j] = s0[j];
            d1[j] = s1[j];
            d2[j] = s2[j];
            if (mk3) {
                float4 a = A4[j], bb = B4[j], r;
                r.x = fmaf(val, a.x, bb.x);
                r.y = fmaf(val, a.y, bb.y);
                r.z = fmaf(val, a.z, bb.z);
                r.w = fmaf(val, a.w, bb.w);
                d3[j] = r;
            } else {
                d3[j] = inb4[j];
            }
            d4[j] = s4[j];
        }
    }
    __syncwarp();

    // scores: lanes 0..24 -> (i,j), loop heads
    if (lane < 25) {
        int i = lane / 5;
        int jj = lane - i * 5;
        const float* qp = S + i * 388;
        const float* kp = S + jj * 388 + 128;
        #pragma unroll
        for (int h = 0; h < 4; h++) {
            float s = 0.0f;
            #pragma unroll
            for (int d = 0; d < 32; d++) s += qp[h * 32 + d] * kp[h * 32 + d];
            S[SC_OFF + h * 25 + lane] = s * 0.17677669529663687f;  // 1/sqrt(32)
        }
    }
    __syncwarp();

    // row stats: lanes 0..19 -> (h,i)
    if (lane < 20) {
        int h = lane / 5;
        int i = lane - h * 5;
        const float* sp = S + SC_OFF + h * 25 + i * 5;
        float m = sp[0];
        #pragma unroll
        for (int j = 1; j < 5; j++) m = fmaxf(m, sp[j]);
        float sum = 0.0f;
        #pragma unroll
        for (int j = 0; j < 5; j++) sum += __expf(sp[j] - m);
        S[RM_OFF + lane] = m;
        S[RS_OFF + lane] = 1.0f / sum;
    }
    __syncwarp();

    // column mean weights: lanes 0..19 -> (h,j):  wk = mean_i attn[i][j]
    if (lane < 20) {
        int h = lane / 5;
        int jj = lane - h * 5;
        float acc = 0.0f;
        #pragma unroll
        for (int i = 0; i < 5; i++)
            acc += __expf(S[SC_OFF + h * 25 + i * 5 + jj] - S[RM_OFF + h * 5 + i]) * S[RS_OFF + h * 5 + i];
        S[WK_OFF + lane] = acc * 0.2f;
    }
    __syncwarp();

    // composed[e] = sum_j wk[h(e)][j] * v_j[e]
    #pragma unroll
    for (int hh = 0; hh < 4; hh++) {
        int e = hh * 32 + lane;
        float c = 0.0f;
        #pragma unroll
        for (int j = 0; j < 5; j++)
            c += S[WK_OFF + hh * 5 + j] * S[j * 388 + 256 + e];
        g_composed[(size_t)n * E_DIM + e] = c;
    }
}

// ---------------- G: out[n][o] = bc[o] + composed[n] . Wc[o] -----------------
// 128x128 tile, K=128 resident in smem (k-major, pitch 129 -> conflict-free
// transpose STS and conflict-free strided scalar LDS), 256 threads, 8x8/thread
#define GP 129
#define GEMM_SMEM_BYTES (2 * 128 * GP * 4)

__global__ void __launch_bounds__(256) gemm_kernel(float* __restrict__ out)
{
    extern __shared__ float sh[];
    float* As = sh;                 // As[e][m]
    float* Bs = sh + 128 * GP;      // Bs[e][o]

    const int o0 = blockIdx.x * 128;
    const int n0 = blockIdx.y * 128;
    const int tid = threadIdx.x;

    // cooperative transpose loads: lanes sweep e (coalesced LDG.32),
    // STS bank = (e + m) % 32 -> conflict-free
    {
        int e = tid & 127;
        int mb = tid >> 7;  // 0 or 1
        const float* Ag = g_composed + (size_t)n0 * E_DIM;
        const float* Bg = g_Wc + (size_t)o0 * E_DIM;
        #pragma unroll 8
        for (int r = 0; r < 64; r++) {
            int m = mb + r * 2;
            As[e * GP + m] = Ag[(size_t)m * E_DIM + e];
        }
        #pragma unroll 8
        for (int r = 0; r < 64; r++) {
            int m = mb + r * 2;
            Bs[e * GP + m] = Bg[(size_t)m * E_DIM + e];
        }
    }
    __syncthreads();

    const int tn = tid & 15;   // col group base (stride-16 tiles -> conflict-free LDS)
    const int tm = tid >> 4;   // row group base

    float acc[8][8];
    #pragma unroll
    for (int i = 0; i < 8; i++)
        #pragma unroll
        for (int j = 0; j < 8; j++) acc[i][j] = 0.0f;

    #pragma unroll 4
    for (int k = 0; k < 128; k++) {
        float a[8], b[8];
        const float* ak = As + k * GP;
        const float* bk = Bs + k * GP;
        #pragma unroll
        for (int i = 0; i < 8; i++) a[i] = ak[tm + 16 * i];
        #pragma unroll
        for (int j = 0; j < 8; j++) b[j] = bk[tn + 16 * j];
        #pragma unroll
        for (int i = 0; i < 8; i++)
            #pragma unroll
            for (int j = 0; j < 8; j++) acc[i][j] = fmaf(a[i], b[j], acc[i][j]);
    }

    float bcv[8];
    #pragma unroll
    for (int j = 0; j < 8; j++) bcv[j] = g_bc[o0 + tn + 16 * j];

    #pragma unroll
    for (int i = 0; i < 8; i++) {
        int row = n0 + tm + 16 * i;
        float* orow = out + (size_t)row * OUT_DIM + o0;
        #pragma unroll
        for (int j = 0; j < 8; j++)
            orow[tn + 16 * j] = acc[i][j] + bcv[j];
    }
}

// ---------------- launch -----------------------------------------------------
extern "C" void kernel_launch(void* const* d_in, const int* in_sizes, int n_in,
                              void* d_out, int out_size)
{
    const int*   device_ids = (const int*)d_in[0];
    const int*   pseudo_ids = (const int*)d_in[1];
    const int*   attr_ids   = (const int*)d_in[2];
    const int*   unit_ids   = (const int*)d_in[3];
    const float* values     = (const float*)d_in[4];
    const int*   mask       = (const int*)d_in[5];
    const float* dev_table  = (const float*)d_in[6];
    const float* pse_table  = (const float*)d_in[7];
    const float* attr_table = (const float*)d_in[8];
    const float* unit_table = (const float*)d_in[9];
    const float* val_w      = (const float*)d_in[10];
    const float* val_b      = (const float*)d_in[11];
    const float* in_proj_w  = (const float*)d_in[12];
    const float* in_proj_b  = (const float*)d_in[13];
    const float* out_proj_w = (const float*)d_in[14];
    const float* out_proj_b = (const float*)d_in[15];
    const float* out_w      = (const float*)d_in[16];
    const float* out_b      = (const float*)d_in[17];
    float* out = (float*)d_out;

    precompute_qkv_kernel<<<142, 384>>>(dev_table, pse_table, attr_table, unit_table,
                                        val_w, val_b, in_proj_w, in_proj_b);
    precompute_wc_kernel<<<768, 128>>>(out_w, out_proj_w, out_proj_b, out_b);

    attn_kernel<<<N_TOT / 4, 128>>>(device_ids, pseudo_ids, attr_ids, unit_ids,
                                    values, mask, in_proj_b);

    cudaFuncSetAttribute(gemm_kernel, cudaFuncAttributeMaxDynamicSharedMemorySize,
                         GEMM_SMEM_BYTES);
    gemm_kernel<<<dim3(OUT_DIM / 128, N_TOT / 128), 256, GEMM_SMEM_BYTES>>>(out);
}

// round 3
// speedup vs baseline: 2.0199x; 2.0199x over previous
#include <cuda_runtime.h>
#include <cuda_bf16.h>
#include <cstdint>

#define N_TOT   131072
#define E_DIM   128
#define QKV_DIM 384
#define OUT_DIM 768

// ---------------- device scratch ---------------------------------------------
__device__ float g_tab_qkv[140 * QKV_DIM];
__device__ float g_valA[QKV_DIM];
__device__ float g_valB[QKV_DIM];
__device__ float g_bc[OUT_DIM];
__device__ __nv_bfloat16 g_Ahi[(size_t)N_TOT * E_DIM];
__device__ __nv_bfloat16 g_Alo[(size_t)N_TOT * E_DIM];
__device__ __nv_bfloat16 g_Bhi[OUT_DIM * E_DIM];
__device__ __nv_bfloat16 g_Blo[OUT_DIM * E_DIM];

// ---------------- helpers ----------------------------------------------------
__device__ __forceinline__ uint32_t smem_u32(const void* p) {
    uint32_t a;
    asm("{ .reg .u64 t; cvta.to.shared.u64 t, %1; cvt.u32.u64 %0, t; }" : "=r"(a) : "l"(p));
    return a;
}
__device__ __forceinline__ void ldsm4(uint32_t& r0, uint32_t& r1, uint32_t& r2, uint32_t& r3,
                                      uint32_t addr) {
    asm volatile("ldmatrix.sync.aligned.m8n8.x4.shared.b16 {%0,%1,%2,%3}, [%4];"
                 : "=r"(r0), "=r"(r1), "=r"(r2), "=r"(r3) : "r"(addr));
}
__device__ __forceinline__ void mma16816(float* c, const uint32_t* a, const uint32_t* b) {
    asm volatile(
        "mma.sync.aligned.m16n8k16.row.col.f32.bf16.bf16.f32 "
        "{%0,%1,%2,%3}, {%4,%5,%6,%7}, {%8,%9}, {%0,%1,%2,%3};"
        : "+f"(c[0]), "+f"(c[1]), "+f"(c[2]), "+f"(c[3])
        : "r"(a[0]), "r"(a[1]), "r"(a[2]), "r"(a[3]), "r"(b[0]), "r"(b[1]));
}

// ---------------- P1: per-table qkv rows + value-linear A/B ------------------
__global__ void precompute_qkv_kernel(
    const float* __restrict__ dev_t, const float* __restrict__ pse_t,
    const float* __restrict__ attr_t, const float* __restrict__ unit_t,
    const float* __restrict__ val_w, const float* __restrict__ val_b,
    const float* __restrict__ W, const float* __restrict__ b)
{
    __shared__ float emb[E_DIM];
    int blk = blockIdx.x;
    int j = threadIdx.x;

    const float* src;
    float* dst;
    int has_bias = 1;
    if (blk < 10)        { src = dev_t  + blk * E_DIM;         dst = g_tab_qkv + blk * QKV_DIM; }
    else if (blk < 20)   { src = pse_t  + (blk - 10) * E_DIM;  dst = g_tab_qkv + blk * QKV_DIM; }
    else if (blk < 120)  { src = attr_t + (blk - 20) * E_DIM;  dst = g_tab_qkv + blk * QKV_DIM; }
    else if (blk < 140)  { src = unit_t + (blk - 120) * E_DIM; dst = g_tab_qkv + blk * QKV_DIM; }
    else if (blk == 140) { src = val_w; dst = g_valA; has_bias = 0; }
    else                 { src = val_b; dst = g_valB; }

    if (j < E_DIM) emb[j] = src[j];
    __syncthreads();

    const float4* Wr = (const float4*)(W + (size_t)j * E_DIM);
    const float4* em = (const float4*)emb;
    float acc = has_bias ? b[j] : 0.0f;
    #pragma unroll
    for (int e4 = 0; e4 < E_DIM / 4; e4++) {
        float4 w = Wr[e4];
        float4 v = em[e4];
        acc += w.x * v.x + w.y * v.y + w.z * v.z + w.w * v.w;
    }
    dst[j] = acc;
}

// ---------------- P2: Wc = out_w @ out_proj_w  (bf16 hi/lo) ------------------
__global__ void precompute_wc_kernel(
    const float* __restrict__ out_w, const float* __restrict__ out_proj_w,
    const float* __restrict__ out_proj_b, const float* __restrict__ out_b)
{
    __shared__ float row[E_DIM];
    int o = blockIdx.x;
    int e = threadIdx.x;
    row[e] = out_w[(size_t)o * E_DIM + e];
    __syncthreads();

    float acc = 0.0f;
    #pragma unroll 8
    for (int m = 0; m < E_DIM; m++)
        acc += row[m] * out_proj_w[(size_t)m * E_DIM + e];

    __nv_bfloat16 hi = __float2bfloat16(acc);
    g_Bhi[(size_t)o * E_DIM + e] = hi;
    g_Blo[(size_t)o * E_DIM + e] = __float2bfloat16(acc - __bfloat162float(hi));

    if (e == 0) {
        float bb = out_b[o];
        for (int m = 0; m < E_DIM; m++) bb += row[m] * out_proj_b[m];
        g_bc[o] = bb;
    }
}

// ---------------- A: attention, one warp per row -----------------------------
#define SMW 2112
#define SC_OFF 1952
#define RM_OFF 2052
#define RS_OFF 2072
#define WK_OFF 2092

__global__ void __launch_bounds__(128) attn_kernel(
    const int* __restrict__ dev_ids, const int* __restrict__ pse_ids,
    const int* __restrict__ attr_ids, const int* __restrict__ unit_ids,
    const float* __restrict__ values, const int* __restrict__ mask,
    const float* __restrict__ inb)
{
    __shared__ float sm[4 * SMW];
    int w = threadIdx.x >> 5;
    int lane = threadIdx.x & 31;
    int n = blockIdx.x * 4 + w;
    float* S = sm + w * SMW;

    int id0 = dev_ids[n];
    int id1 = pse_ids[n];
    int id2 = attr_ids[n];
    int id4 = unit_ids[n];
    float val = values[n];
    int mk0 = mask[n * 5 + 0];
    int mk1 = mask[n * 5 + 1];
    int mk2 = mask[n * 5 + 2];
    int mk3 = mask[n * 5 + 3];
    int mk4 = mask[n * 5 + 4];

    const float4* inb4 = (const float4*)inb;
    const float4* r0 = (const float4*)(g_tab_qkv + id0 * QKV_DIM);
    const float4* r1 = (const float4*)(g_tab_qkv + (10 + id1) * QKV_DIM);
    const float4* r2 = (const float4*)(g_tab_qkv + (20 + id2) * QKV_DIM);
    const float4* r4 = (const float4*)(g_tab_qkv + (120 + id4) * QKV_DIM);

    {
        const float4* s0 = mk0 ? r0 : inb4;
        const float4* s1 = mk1 ? r1 : inb4;
        const float4* s2 = mk2 ? r2 : inb4;
        const float4* s4 = mk4 ? r4 : inb4;
        float4* d0 = (float4*)(S + 0 * 388);
        float4* d1 = (float4*)(S + 1 * 388);
        float4* d2 = (float4*)(S + 2 * 388);
        float4* d3 = (float4*)(S + 3 * 388);
        float4* d4 = (float4*)(S + 4 * 388);
        const float4* A4 = (const float4*)g_valA;
        const float4* B4 = (const float4*)g_valB;
        #pragma unroll
        for (int it = 0; it < 3; it++) {
            int j = lane + it * 32;
            d0[j] = s0[j];
            d1[j] = s1[j];
            d2[j] = s2[j];
            if (mk3) {
                float4 a = A4[j], bb = B4[j], r;
                r.x = fmaf(val, a.x, bb.x);
                r.y = fmaf(val, a.y, bb.y);
                r.z = fmaf(val, a.z, bb.z);
                r.w = fmaf(val, a.w, bb.w);
                d3[j] = r;
            } else {
                d3[j] = inb4[j];
            }
            d4[j] = s4[j];
        }
    }
    __syncwarp();

    if (lane < 25) {
        int i = lane / 5;
        int jj = lane - i * 5;
        const float* qp = S + i * 388;
        const float* kp = S + jj * 388 + 128;
        #pragma unroll
        for (int h = 0; h < 4; h++) {
            float s = 0.0f;
            #pragma unroll
            for (int d = 0; d < 32; d++) s += qp[h * 32 + d] * kp[h * 32 + d];
            S[SC_OFF + h * 25 + lane] = s * 0.17677669529663687f;
        }
    }
    __syncwarp();

    if (lane < 20) {
        int h = lane / 5;
        int i = lane - h * 5;
        const float* sp = S + SC_OFF + h * 25 + i * 5;
        float m = sp[0];
        #pragma unroll
        for (int j = 1; j < 5; j++) m = fmaxf(m, sp[j]);
        float sum = 0.0f;
        #pragma unroll
        for (int j = 0; j < 5; j++) sum += __expf(sp[j] - m);
        S[RM_OFF + lane] = m;
        S[RS_OFF + lane] = 1.0f / sum;
    }
    __syncwarp();

    if (lane < 20) {
        int h = lane / 5;
        int jj = lane - h * 5;
        float acc = 0.0f;
        #pragma unroll
        for (int i = 0; i < 5; i++)
            acc += __expf(S[SC_OFF + h * 25 + i * 5 + jj] - S[RM_OFF + h * 5 + i]) * S[RS_OFF + h * 5 + i];
        S[WK_OFF + lane] = acc * 0.2f;
    }
    __syncwarp();

    #pragma unroll
    for (int hh = 0; hh < 4; hh++) {
        int e = hh * 32 + lane;
        float c = 0.0f;
        #pragma unroll
        for (int j = 0; j < 5; j++)
            c += S[WK_OFF + hh * 5 + j] * S[j * 388 + 256 + e];
        __nv_bfloat16 hi = __float2bfloat16(c);
        g_Ahi[(size_t)n * E_DIM + e] = hi;
        g_Alo[(size_t)n * E_DIM + e] = __float2bfloat16(c - __bfloat162float(hi));
    }
}

// ---------------- G: mma.sync bf16 split-precision GEMM ----------------------
// out[n][o] = bc[o] + A[n] . B[o],   A.B = Ahi.Bhi + Alo.Bhi + Ahi.Blo
// CTA: 256 thr, tile 128(m) x 128(n), K=128 resident. pitch 136 bf16 (272B)
#define GP 136
#define TILE_ELEMS (128 * GP)
#define G_SMEM_BYTES (4 * TILE_ELEMS * 2)

__device__ __forceinline__ void load_tile_p(__nv_bfloat16* dst,
                                            const __nv_bfloat16* __restrict__ src, int tid) {
    #pragma unroll
    for (int it = 0; it < 8; it++) {
        int idx = it * 256 + tid;       // 2048 uint4
        int row = idx >> 4;
        int c8 = (idx & 15) << 3;
        *(uint4*)(dst + row * GP + c8) = *(const uint4*)(src + row * E_DIM + c8);
    }
}

__global__ void __launch_bounds__(256) gemm_mma_kernel(float* __restrict__ out)
{
    extern __shared__ __nv_bfloat16 smem[];
    __nv_bfloat16* sAhi = smem;
    __nv_bfloat16* sAlo = smem + TILE_ELEMS;
    __nv_bfloat16* sBhi = smem + 2 * TILE_ELEMS;
    __nv_bfloat16* sBlo = smem + 3 * TILE_ELEMS;

    const int tid = threadIdx.x;
    const int wid = tid >> 5;
    const int lane = tid & 31;
    const int n0 = blockIdx.x * 128;   // out-col tile (fast index -> B L2-resident)
    const int m0 = blockIdx.y * 128;

    load_tile_p(sAhi, g_Ahi + (size_t)m0 * E_DIM, tid);
    load_tile_p(sAlo, g_Alo + (size_t)m0 * E_DIM, tid);
    load_tile_p(sBhi, g_Bhi + (size_t)n0 * E_DIM, tid);
    load_tile_p(sBlo, g_Blo + (size_t)n0 * E_DIM, tid);
    __syncthreads();

    const int wm = (wid & 3) * 32;     // warp m offset
    const int wn = (wid >> 2) * 64;    // warp n offset

    // ldmatrix lane->address offsets (bytes)
    const uint32_t aLane = ((wm + (lane & 15)) * GP + ((lane >> 4) << 3)) * 2;
    const uint32_t bLane = ((wn + (lane & 7) + ((lane & 16) >> 1)) * GP + (lane & 8)) * 2;

    const uint32_t aHiB = smem_u32(sAhi), aLoB = smem_u32(sAlo);
    const uint32_t bHiB = smem_u32(sBhi), bLoB = smem_u32(sBlo);
    const uint32_t aBases[3] = {aHiB, aLoB, aHiB};
    const uint32_t bBases[3] = {bHiB, bHiB, bLoB};

    float c[2][8][4];
    #pragma unroll
    for (int mi = 0; mi < 2; mi++)
        #pragma unroll
        for (int ni = 0; ni < 8; ni++)
            #pragma unroll
            for (int q = 0; q < 4; q++) c[mi][ni][q] = 0.0f;

    #pragma unroll 1
    for (int p = 0; p < 3; p++) {
        const uint32_t aB = aBases[p] + aLane;
        const uint32_t bB = bBases[p] + bLane;
        #pragma unroll
        for (int ks = 0; ks < 8; ks++) {
            const uint32_t kOff = (uint32_t)(ks * 16 * 2);
            uint32_t a[2][4];
            ldsm4(a[0][0], a[0][1], a[0][2], a[0][3], aB + kOff);
            ldsm4(a[1][0], a[1][1], a[1][2], a[1][3], aB + kOff + 16 * GP * 2);
            uint32_t b[8][2];
            #pragma unroll
            for (int bj = 0; bj < 4; bj++) {
                ldsm4(b[2 * bj][0], b[2 * bj][1], b[2 * bj + 1][0], b[2 * bj + 1][1],
                      bB + kOff + bj * (16 * GP * 2));
            }
            #pragma unroll
            for (int mi = 0; mi < 2; mi++)
                #pragma unroll
                for (int ni = 0; ni < 8; ni++)
                    mma16816(c[mi][ni], a[mi], b[ni]);
        }
    }

    // epilogue: + bc, direct float2 stores
    const int mg = m0 + wm + (lane >> 2);
    const int ngb = n0 + wn + 2 * (lane & 3);
    #pragma unroll
    for (int ni = 0; ni < 8; ni++) {
        int col = ngb + ni * 8;
        float2 bc2 = *(const float2*)(g_bc + col);
        #pragma unroll
        for (int mi = 0; mi < 2; mi++) {
            int r0 = mg + mi * 16;
            float2 v0 = {c[mi][ni][0] + bc2.x, c[mi][ni][1] + bc2.y};
            float2 v1 = {c[mi][ni][2] + bc2.x, c[mi][ni][3] + bc2.y};
            *(float2*)(out + (size_t)r0 * OUT_DIM + col) = v0;
            *(float2*)(out + (size_t)(r0 + 8) * OUT_DIM + col) = v1;
        }
    }
}

// ---------------- launch -----------------------------------------------------
extern "C" void kernel_launch(void* const* d_in, const int* in_sizes, int n_in,
                              void* d_out, int out_size)
{
    const int*   device_ids = (const int*)d_in[0];
    const int*   pseudo_ids = (const int*)d_in[1];
    const int*   attr_ids   = (const int*)d_in[2];
    const int*   unit_ids   = (const int*)d_in[3];
    const float* values     = (const float*)d_in[4];
    const int*   mask       = (const int*)d_in[5];
    const float* dev_table  = (const float*)d_in[6];
    const float* pse_table  = (const float*)d_in[7];
    const float* attr_table = (const float*)d_in[8];
    const float* unit_table = (const float*)d_in[9];
    const float* val_w      = (const float*)d_in[10];
    const float* val_b      = (const float*)d_in[11];
    const float* in_proj_w  = (const float*)d_in[12];
    const float* in_proj_b  = (const float*)d_in[13];
    const float* out_proj_w = (const float*)d_in[14];
    const float* out_proj_b = (const float*)d_in[15];
    const float* out_w      = (const float*)d_in[16];
    const float* out_b      = (const float*)d_in[17];
    float* out = (float*)d_out;

    precompute_qkv_kernel<<<142, 384>>>(dev_table, pse_table, attr_table, unit_table,
                                        val_w, val_b, in_proj_w, in_proj_b);
    precompute_wc_kernel<<<768, 128>>>(out_w, out_proj_w, out_proj_b, out_b);

    attn_kernel<<<N_TOT / 4, 128>>>(device_ids, pseudo_ids, attr_ids, unit_ids,
                                    values, mask, in_proj_b);

    cudaFuncSetAttribute(gemm_mma_kernel, cudaFuncAttributeMaxDynamicSharedMemorySize,
                         G_SMEM_BYTES);
    gemm_mma_kernel<<<dim3(OUT_DIM / 128, N_TOT / 128), 256, G_SMEM_BYTES>>>(out);
}

// round 4
// speedup vs baseline: 2.7053x; 1.3393x over previous
#include <cuda_runtime.h>
#include <cuda_bf16.h>
#include <cstdint>

#define N_TOT   131072
#define E_DIM   128
#define QKV_DIM 384
#define OUT_DIM 768
#define NROWS   141   // 140 table rows + bias row (masked token)

// ---------------- device scratch ---------------------------------------------
__device__ float g_tab_qkv[NROWS * QKV_DIM];
__device__ float g_valA[QKV_DIM];
__device__ float g_valB[QKV_DIM];
__device__ float g_bc[OUT_DIM];
__device__ float4 g_Spp[NROWS * NROWS];   // [ri*141+rj] -> 4 head scores (pre-scaled)
__device__ float4 g_SqA[NROWS];
__device__ float4 g_SqB[NROWS];
__device__ float4 g_SAk[NROWS];
__device__ float4 g_SBk[NROWS];
__device__ float4 g_c3[3];                // cAA, cAB, cBB
__device__ float g_vtab[NROWS * E_DIM];
__device__ __nv_bfloat16 g_Ahi[(size_t)N_TOT * E_DIM];
__device__ __nv_bfloat16 g_Alo[(size_t)N_TOT * E_DIM];
__device__ __nv_bfloat16 g_Bhi[OUT_DIM * E_DIM];
__device__ __nv_bfloat16 g_Blo[OUT_DIM * E_DIM];

#define SCALE 0.17677669529663687f  // 1/sqrt(32)

// ---------------- helpers ----------------------------------------------------
__device__ __forceinline__ uint32_t smem_u32(const void* p) {
    uint32_t a;
    asm("{ .reg .u64 t; cvta.to.shared.u64 t, %1; cvt.u32.u64 %0, t; }" : "=r"(a) : "l"(p));
    return a;
}
__device__ __forceinline__ void ldsm4(uint32_t& r0, uint32_t& r1, uint32_t& r2, uint32_t& r3,
                                      uint32_t addr) {
    asm volatile("ldmatrix.sync.aligned.m8n8.x4.shared.b16 {%0,%1,%2,%3}, [%4];"
                 : "=r"(r0), "=r"(r1), "=r"(r2), "=r"(r3) : "r"(addr));
}
__device__ __forceinline__ void mma16816(float* c, const uint32_t* a, const uint32_t* b) {
    asm volatile(
        "mma.sync.aligned.m16n8k16.row.col.f32.bf16.bf16.f32 "
        "{%0,%1,%2,%3}, {%4,%5,%6,%7}, {%8,%9}, {%0,%1,%2,%3};"
        : "+f"(c[0]), "+f"(c[1]), "+f"(c[2]), "+f"(c[3])
        : "r"(a[0]), "r"(a[1]), "r"(a[2]), "r"(a[3]), "r"(b[0]), "r"(b[1]));
}

// ---------------- P1: qkv rows for tables + bias row + valA/valB -------------
// grid = 143: 0..139 tables, 140 bias row, 141 valA, 142 valB.  block = 384
__global__ void precompute_qkv_kernel(
    const float* __restrict__ dev_t, const float* __restrict__ pse_t,
    const float* __restrict__ attr_t, const float* __restrict__ unit_t,
    const float* __restrict__ val_w, const float* __restrict__ val_b,
    const float* __restrict__ W, const float* __restrict__ b)
{
    __shared__ float emb[E_DIM];
    int blk = blockIdx.x;
    int j = threadIdx.x;

    const float* src = nullptr;
    float* dst;
    int has_bias = 1;
    if (blk < 10)        { src = dev_t  + blk * E_DIM;         dst = g_tab_qkv + blk * QKV_DIM; }
    else if (blk < 20)   { src = pse_t  + (blk - 10) * E_DIM;  dst = g_tab_qkv + blk * QKV_DIM; }
    else if (blk < 120)  { src = attr_t + (blk - 20) * E_DIM;  dst = g_tab_qkv + blk * QKV_DIM; }
    else if (blk < 140)  { src = unit_t + (blk - 120) * E_DIM; dst = g_tab_qkv + blk * QKV_DIM; }
    else if (blk == 140) { src = nullptr; dst = g_tab_qkv + 140 * QKV_DIM; }  // zero emb
    else if (blk == 141) { src = val_w; dst = g_valA; has_bias = 0; }
    else                 { src = val_b; dst = g_valB; }

    if (j < E_DIM) emb[j] = src ? src[j] : 0.0f;
    __syncthreads();

    const float4* Wr = (const float4*)(W + (size_t)j * E_DIM);
    const float4* em = (const float4*)emb;
    float acc = has_bias ? b[j] : 0.0f;
    #pragma unroll
    for (int e4 = 0; e4 < E_DIM / 4; e4++) {
        float4 w = Wr[e4];
        float4 v = em[e4];
        acc += w.x * v.x + w.y * v.y + w.z * v.z + w.w * v.w;
    }
    dst[j] = acc;
}

// ---------------- P2: Wc = out_w @ out_proj_w  (bf16 hi/lo) ------------------
__global__ void precompute_wc_kernel(
    const float* __restrict__ out_w, const float* __restrict__ out_proj_w,
    const float* __restrict__ out_proj_b, const float* __restrict__ out_b)
{
    __shared__ float row[E_DIM];
    int o = blockIdx.x;
    int e = threadIdx.x;
    row[e] = out_w[(size_t)o * E_DIM + e];
    __syncthreads();

    float acc = 0.0f;
    #pragma unroll 8
    for (int m = 0; m < E_DIM; m++)
        acc += row[m] * out_proj_w[(size_t)m * E_DIM + e];

    __nv_bfloat16 hi = __float2bfloat16(acc);
    g_Bhi[(size_t)o * E_DIM + e] = hi;
    g_Blo[(size_t)o * E_DIM + e] = __float2bfloat16(acc - __bfloat162float(hi));

    if (e == 0) {
        float bb = out_b[o];
        for (int m = 0; m < E_DIM; m++) bb += row[m] * out_proj_b[m];
        g_bc[o] = bb;
    }
}

// ---------------- P3: pairwise score tables + v table ------------------------
__device__ __forceinline__ float dot32(const float* a, const float* b) {
    float s = 0.0f;
    #pragma unroll
    for (int d = 0; d < 32; d++) s += a[d] * b[d];
    return s;
}

__global__ void precompute_tables_kernel()
{
    __shared__ float q[E_DIM];
    int ri = blockIdx.x;
    int t = threadIdx.x;

    q[t] = g_tab_qkv[ri * QKV_DIM + t];
    g_vtab[ri * E_DIM + t] = g_tab_qkv[ri * QKV_DIM + 256 + t];
    __syncthreads();

    for (int rj = t; rj < NROWS; rj += 128) {
        const float* k = g_tab_qkv + rj * QKV_DIM + 128;
        float4 s;
        s.x = SCALE * dot32(q + 0,  k + 0);
        s.y = SCALE * dot32(q + 32, k + 32);
        s.z = SCALE * dot32(q + 64, k + 64);
        s.w = SCALE * dot32(q + 96, k + 96);
        g_Spp[ri * NROWS + rj] = s;
    }

    if (t < 4) {
        int h = t;
        ((float*)&g_SqA[ri])[h] = SCALE * dot32(q + 32 * h, g_valA + 128 + 32 * h);
        ((float*)&g_SqB[ri])[h] = SCALE * dot32(q + 32 * h, g_valB + 128 + 32 * h);
    } else if (t < 8) {
        int h = t - 4;
        const float* kr = g_tab_qkv + ri * QKV_DIM + 128 + 32 * h;
        ((float*)&g_SAk[ri])[h] = SCALE * dot32(g_valA + 32 * h, kr);
        ((float*)&g_SBk[ri])[h] = SCALE * dot32(g_valB + 32 * h, kr);
    }

    if (ri == 0 && t >= 8 && t < 12) {
        int h = t - 8;
        const float* Aq = g_valA + 32 * h;
        const float* Bq = g_valB + 32 * h;
        const float* Ak = g_valA + 128 + 32 * h;
        const float* Bk = g_valB + 128 + 32 * h;
        ((float*)&g_c3[0])[h] = SCALE * dot32(Aq, Ak);
        ((float*)&g_c3[1])[h] = SCALE * (dot32(Aq, Bk) + dot32(Bq, Ak));
        ((float*)&g_c3[2])[h] = SCALE * dot32(Bq, Bk);
    }
}

// ---------------- A: attention via tables, one warp per row ------------------
#define SMW 160
#define SC_OFF 0
#define RM_OFF 100
#define RS_OFF 120
#define WK_OFF 140

__global__ void __launch_bounds__(128) attn_kernel(
    const int* __restrict__ dev_ids, const int* __restrict__ pse_ids,
    const int* __restrict__ attr_ids, const int* __restrict__ unit_ids,
    const float* __restrict__ values, const int* __restrict__ mask)
{
    __shared__ float sm[4 * SMW];
    int w = threadIdx.x >> 5;
    int lane = threadIdx.x & 31;
    int n = blockIdx.x * 4 + w;
    float* S = sm + w * SMW;

    int mk0 = mask[n * 5 + 0];
    int mk1 = mask[n * 5 + 1];
    int mk2 = mask[n * 5 + 2];
    int mk3 = mask[n * 5 + 3];
    int mk4 = mask[n * 5 + 4];
    int r0 = mk0 ? dev_ids[n]        : 140;
    int r1 = mk1 ? 10 + pse_ids[n]   : 140;
    int r2 = mk2 ? 20 + attr_ids[n]  : 140;
    int r4 = mk4 ? 120 + unit_ids[n] : 140;
    float val = values[n];

    if (lane < 25) {
        int i = lane / 5;
        int j = lane - i * 5;
        int ri = (i == 0) ? r0 : (i == 1) ? r1 : (i == 2) ? r2 : (i == 3) ? 140 : r4;
        int rj = (j == 0) ? r0 : (j == 1) ? r1 : (j == 2) ? r2 : (j == 3) ? 140 : r4;
        float4 s;
        if (mk3 && (i == 3 || j == 3)) {
            if (i == 3 && j == 3) {
                float4 cAA = g_c3[0], cAB = g_c3[1], cBB = g_c3[2];
                float v2 = val * val;
                s.x = fmaf(v2, cAA.x, fmaf(val, cAB.x, cBB.x));
                s.y = fmaf(v2, cAA.y, fmaf(val, cAB.y, cBB.y));
                s.z = fmaf(v2, cAA.z, fmaf(val, cAB.z, cBB.z));
                s.w = fmaf(v2, cAA.w, fmaf(val, cAB.w, cBB.w));
            } else if (j == 3) {
                float4 a = g_SqA[ri], b = g_SqB[ri];
                s.x = fmaf(val, a.x, b.x);
                s.y = fmaf(val, a.y, b.y);
                s.z = fmaf(val, a.z, b.z);
                s.w = fmaf(val, a.w, b.w);
            } else {
                float4 a = g_SAk[rj], b = g_SBk[rj];
                s.x = fmaf(val, a.x, b.x);
                s.y = fmaf(val, a.y, b.y);
                s.z = fmaf(val, a.z, b.z);
                s.w = fmaf(val, a.w, b.w);
            }
        } else {
            s = g_Spp[ri * NROWS + rj];
        }
        S[SC_OFF + 0 * 25 + lane] = s.x;
        S[SC_OFF + 1 * 25 + lane] = s.y;
        S[SC_OFF + 2 * 25 + lane] = s.z;
        S[SC_OFF + 3 * 25 + lane] = s.w;
    }
    __syncwarp();

    if (lane < 20) {
        int h = lane / 5;
        int i = lane - h * 5;
        const float* sp = S + SC_OFF + h * 25 + i * 5;
        float m = sp[0];
        #pragma unroll
        for (int j = 1; j < 5; j++) m = fmaxf(m, sp[j]);
        float sum = 0.0f;
        #pragma unroll
        for (int j = 0; j < 5; j++) sum += __expf(sp[j] - m);
        S[RM_OFF + lane] = m;
        S[RS_OFF + lane] = 1.0f / sum;
    }
    __syncwarp();

    if (lane < 20) {
        int h = lane / 5;
        int jj = lane - h * 5;
        float acc = 0.0f;
        #pragma unroll
        for (int i = 0; i < 5; i++)
            acc += __expf(S[SC_OFF + h * 25 + i * 5 + jj] - S[RM_OFF + h * 5 + i]) * S[RS_OFF + h * 5 + i];
        S[WK_OFF + lane] = acc * 0.2f;
    }
    __syncwarp();

    const float* v0 = g_vtab + r0 * E_DIM;
    const float* v1 = g_vtab + r1 * E_DIM;
    const float* v2 = g_vtab + r2 * E_DIM;
    const float* v4 = g_vtab + r4 * E_DIM;
    const float* vb = g_vtab + 140 * E_DIM;

    #pragma unroll
    for (int hh = 0; hh < 4; hh++) {
        int e = hh * 32 + lane;
        float wk0 = S[WK_OFF + hh * 5 + 0];
        float wk1 = S[WK_OFF + hh * 5 + 1];
        float wk2 = S[WK_OFF + hh * 5 + 2];
        float wk3 = S[WK_OFF + hh * 5 + 3];
        float wk4 = S[WK_OFF + hh * 5 + 4];
        float v3e = mk3 ? fmaf(val, g_valA[256 + e], g_valB[256 + e]) : vb[e];
        float c = wk0 * v0[e] + wk1 * v1[e] + wk2 * v2[e] + wk3 * v3e + wk4 * v4[e];
        __nv_bfloat16 hi = __float2bfloat16(c);
        g_Ahi[(size_t)n * E_DIM + e] = hi;
        g_Alo[(size_t)n * E_DIM + e] = __float2bfloat16(c - __bfloat162float(hi));
    }
}

// ---------------- G: mma.sync bf16 split GEMM, 128m x 64n, 2 CTA/SM ----------
#define GP 136
#define A_ELEMS (128 * GP)
#define B_ELEMS (64 * GP)
#define G_SMEM_BYTES ((2 * A_ELEMS + 2 * B_ELEMS) * 2)

template <int ROWS>
__device__ __forceinline__ void load_tile_p(__nv_bfloat16* dst,
                                            const __nv_bfloat16* __restrict__ src, int tid) {
    #pragma unroll
    for (int it = 0; it < ROWS / 16; it++) {
        int idx = it * 256 + tid;
        int row = idx >> 4;
        int c8 = (idx & 15) << 3;
        *(uint4*)(dst + row * GP + c8) = *(const uint4*)(src + row * E_DIM + c8);
    }
}

__global__ void __launch_bounds__(256, 2) gemm_mma_kernel(float* __restrict__ out)
{
    extern __shared__ __nv_bfloat16 smem[];
    __nv_bfloat16* sAhi = smem;
    __nv_bfloat16* sAlo = smem + A_ELEMS;
    __nv_bfloat16* sBhi = smem + 2 * A_ELEMS;
    __nv_bfloat16* sBlo = smem + 2 * A_ELEMS + B_ELEMS;

    const int tid = threadIdx.x;
    const int wid = tid >> 5;
    const int lane = tid & 31;
    const int n0 = blockIdx.x * 64;
    const int m0 = blockIdx.y * 128;

    load_tile_p<128>(sAhi, g_Ahi + (size_t)m0 * E_DIM, tid);
    load_tile_p<128>(sAlo, g_Alo + (size_t)m0 * E_DIM, tid);
    load_tile_p<64>(sBhi, g_Bhi + (size_t)n0 * E_DIM, tid);
    load_tile_p<64>(sBlo, g_Blo + (size_t)n0 * E_DIM, tid);
    __syncthreads();

    const int wm = (wid & 3) * 32;
    const int wn = (wid >> 2) * 32;

    const uint32_t aLane = ((wm + (lane & 15)) * GP + ((lane >> 4) << 3)) * 2;
    const uint32_t bLane = ((wn + (lane & 7) + ((lane & 16) >> 1)) * GP + (lane & 8)) * 2;

    const uint32_t aHiB = smem_u32(sAhi), aLoB = smem_u32(sAlo);
    const uint32_t bHiB = smem_u32(sBhi), bLoB = smem_u32(sBlo);
    const uint32_t aBases[3] = {aHiB, aLoB, aHiB};
    const uint32_t bBases[3] = {bHiB, bHiB, bLoB};

    float c[2][4][4];
    #pragma unroll
    for (int mi = 0; mi < 2; mi++)
        #pragma unroll
        for (int ni = 0; ni < 4; ni++)
            #pragma unroll
            for (int q = 0; q < 4; q++) c[mi][ni][q] = 0.0f;

    #pragma unroll 1
    for (int p = 0; p < 3; p++) {
        const uint32_t aB = aBases[p] + aLane;
        const uint32_t bB = bBases[p] + bLane;
        #pragma unroll
        for (int ks = 0; ks < 8; ks++) {
            const uint32_t kOff = (uint32_t)(ks * 16 * 2);
            uint32_t a[2][4];
            ldsm4(a[0][0], a[0][1], a[0][2], a[0][3], aB + kOff);
            ldsm4(a[1][0], a[1][1], a[1][2], a[1][3], aB + kOff + 16 * GP * 2);
            uint32_t b[4][2];
            #pragma unroll
            for (int bj = 0; bj < 2; bj++) {
                ldsm4(b[2 * bj][0], b[2 * bj][1], b[2 * bj + 1][0], b[2 * bj + 1][1],
                      bB + kOff + bj * (16 * GP * 2));
            }
            #pragma unroll
            for (int mi = 0; mi < 2; mi++)
                #pragma unroll
                for (int ni = 0; ni < 4; ni++)
                    mma16816(c[mi][ni], a[mi], b[ni]);
        }
    }

    const int mg = m0 + wm + (lane >> 2);
    const int ngb = n0 + wn + 2 * (lane & 3);
    #pragma unroll
    for (int ni = 0; ni < 4; ni++) {
        int col = ngb + ni * 8;
        float2 bc2 = *(const float2*)(g_bc + col);
        #pragma unroll
        for (int mi = 0; mi < 2; mi++) {
            int r0 = mg + mi * 16;
            float2 v0 = {c[mi][ni][0] + bc2.x, c[mi][ni][1] + bc2.y};
            float2 v1 = {c[mi][ni][2] + bc2.x, c[mi][ni][3] + bc2.y};
            *(float2*)(out + (size_t)r0 * OUT_DIM + col) = v0;
            *(float2*)(out + (size_t)(r0 + 8) * OUT_DIM + col) = v1;
        }
    }
}

// ---------------- launch -----------------------------------------------------
extern "C" void kernel_launch(void* const* d_in, const int* in_sizes, int n_in,
                              void* d_out, int out_size)
{
    const int*   device_ids = (const int*)d_in[0];
    const int*   pseudo_ids = (const int*)d_in[1];
    const int*   attr_ids   = (const int*)d_in[2];
    const int*   unit_ids   = (const int*)d_in[3];
    const float* values     = (const float*)d_in[4];
    const int*   mask       = (const int*)d_in[5];
    const float* dev_table  = (const float*)d_in[6];
    const float* pse_table  = (const float*)d_in[7];
    const float* attr_table = (const float*)d_in[8];
    const float* unit_table = (const float*)d_in[9];
    const float* val_w      = (const float*)d_in[10];
    const float* val_b      = (const float*)d_in[11];
    const float* in_proj_w  = (const float*)d_in[12];
    const float* in_proj_b  = (const float*)d_in[13];
    const float* out_proj_w = (const float*)d_in[14];
    const float* out_proj_b = (const float*)d_in[15];
    const float* out_w      = (const float*)d_in[16];
    const float* out_b      = (const float*)d_in[17];
    float* out = (float*)d_out;

    precompute_qkv_kernel<<<143, 384>>>(dev_table, pse_table, attr_table, unit_table,
                                        val_w, val_b, in_proj_w, in_proj_b);
    precompute_wc_kernel<<<768, 128>>>(out_w, out_proj_w, out_proj_b, out_b);
    precompute_tables_kernel<<<NROWS, 128>>>();

    attn_kernel<<<N_TOT / 4, 128>>>(device_ids, pseudo_ids, attr_ids, unit_ids,
                                    values, mask);

    cudaFuncSetAttribute(gemm_mma_kernel, cudaFuncAttributeMaxDynamicSharedMemorySize,
                         G_SMEM_BYTES);
    gemm_mma_kernel<<<dim3(OUT_DIM / 64, N_TOT / 128), 256, G_SMEM_BYTES>>>(out);
}

// round 5
// speedup vs baseline: 3.0894x; 1.1420x over previous
#include <cuda_runtime.h>
#include <cuda_bf16.h>
#include <cstdint>

#define N_TOT   131072
#define E_DIM   128
#define QKV_DIM 384
#define OUT_DIM 768
#define NROWS   141   // 140 table rows + bias row (masked token)

// ---------------- device scratch ---------------------------------------------
__device__ float g_tab_qkv[NROWS * QKV_DIM];
__device__ float g_valA[QKV_DIM];
__device__ float g_valB[QKV_DIM];
__device__ float g_bc[OUT_DIM];
__device__ float4 g_Spp[NROWS * NROWS];   // [ri*141+rj] -> 4 head scores (pre-scaled)
__device__ float4 g_SqA[NROWS];
__device__ float4 g_SqB[NROWS];
__device__ float4 g_SAk[NROWS];
__device__ float4 g_SBk[NROWS];
__device__ float4 g_c3[3];                // cAA, cAB, cBB
__device__ float g_vtab[NROWS * E_DIM];
__device__ __nv_bfloat16 g_Ahi[(size_t)N_TOT * E_DIM];
__device__ __nv_bfloat16 g_Alo[(size_t)N_TOT * E_DIM];
__device__ __nv_bfloat16 g_Bhi[OUT_DIM * E_DIM];
__device__ __nv_bfloat16 g_Blo[OUT_DIM * E_DIM];

#define SCALE 0.17677669529663687f  // 1/sqrt(32)

// ---------------- helpers ----------------------------------------------------
__device__ __forceinline__ uint32_t smem_u32(const void* p) {
    uint32_t a;
    asm("{ .reg .u64 t; cvta.to.shared.u64 t, %1; cvt.u32.u64 %0, t; }" : "=r"(a) : "l"(p));
    return a;
}
__device__ __forceinline__ void ldsm4(uint32_t& r0, uint32_t& r1, uint32_t& r2, uint32_t& r3,
                                      uint32_t addr) {
    asm volatile("ldmatrix.sync.aligned.m8n8.x4.shared.b16 {%0,%1,%2,%3}, [%4];"
                 : "=r"(r0), "=r"(r1), "=r"(r2), "=r"(r3) : "r"(addr));
}
__device__ __forceinline__ void mma16816(float* c, const uint32_t* a, const uint32_t* b) {
    asm volatile(
        "mma.sync.aligned.m16n8k16.row.col.f32.bf16.bf16.f32 "
        "{%0,%1,%2,%3}, {%4,%5,%6,%7}, {%8,%9}, {%0,%1,%2,%3};"
        : "+f"(c[0]), "+f"(c[1]), "+f"(c[2]), "+f"(c[3])
        : "r"(a[0]), "r"(a[1]), "r"(a[2]), "r"(a[3]), "r"(b[0]), "r"(b[1]));
}
__device__ __forceinline__ void cp16(uint32_t dst, const void* src) {
    asm volatile("cp.async.cg.shared.global [%0], [%1], 16;" :: "r"(dst), "l"(src));
}
__device__ __forceinline__ void cp_commit() {
    asm volatile("cp.async.commit_group;" ::: "memory");
}
template <int N>
__device__ __forceinline__ void cp_wait() {
    asm volatile("cp.async.wait_group %0;" :: "n"(N) : "memory");
}

// ---------------- P1: qkv rows for tables + bias row + valA/valB -------------
__global__ void precompute_qkv_kernel(
    const float* __restrict__ dev_t, const float* __restrict__ pse_t,
    const float* __restrict__ attr_t, const float* __restrict__ unit_t,
    const float* __restrict__ val_w, const float* __restrict__ val_b,
    const float* __restrict__ W, const float* __restrict__ b)
{
    __shared__ float emb[E_DIM];
    int blk = blockIdx.x;
    int j = threadIdx.x;

    const float* src = nullptr;
    float* dst;
    int has_bias = 1;
    if (blk < 10)        { src = dev_t  + blk * E_DIM;         dst = g_tab_qkv + blk * QKV_DIM; }
    else if (blk < 20)   { src = pse_t  + (blk - 10) * E_DIM;  dst = g_tab_qkv + blk * QKV_DIM; }
    else if (blk < 120)  { src = attr_t + (blk - 20) * E_DIM;  dst = g_tab_qkv + blk * QKV_DIM; }
    else if (blk < 140)  { src = unit_t + (blk - 120) * E_DIM; dst = g_tab_qkv + blk * QKV_DIM; }
    else if (blk == 140) { src = nullptr; dst = g_tab_qkv + 140 * QKV_DIM; }
    else if (blk == 141) { src = val_w; dst = g_valA; has_bias = 0; }
    else                 { src = val_b; dst = g_valB; }

    if (j < E_DIM) emb[j] = src ? src[j] : 0.0f;
    __syncthreads();

    const float4* Wr = (const float4*)(W + (size_t)j * E_DIM);
    const float4* em = (const float4*)emb;
    float acc = has_bias ? b[j] : 0.0f;
    #pragma unroll
    for (int e4 = 0; e4 < E_DIM / 4; e4++) {
        float4 w = Wr[e4];
        float4 v = em[e4];
        acc += w.x * v.x + w.y * v.y + w.z * v.z + w.w * v.w;
    }
    dst[j] = acc;
}

// ---------------- P2: Wc = out_w @ out_proj_w  (bf16 hi/lo) ------------------
__global__ void precompute_wc_kernel(
    const float* __restrict__ out_w, const float* __restrict__ out_proj_w,
    const float* __restrict__ out_proj_b, const float* __restrict__ out_b)
{
    __shared__ float row[E_DIM];
    int o = blockIdx.x;
    int e = threadIdx.x;
    row[e] = out_w[(size_t)o * E_DIM + e];
    __syncthreads();

    float acc = 0.0f;
    #pragma unroll 8
    for (int m = 0; m < E_DIM; m++)
        acc += row[m] * out_proj_w[(size_t)m * E_DIM + e];

    __nv_bfloat16 hi = __float2bfloat16(acc);
    g_Bhi[(size_t)o * E_DIM + e] = hi;
    g_Blo[(size_t)o * E_DIM + e] = __float2bfloat16(acc - __bfloat162float(hi));

    if (e == 0) {
        float bb = out_b[o];
        for (int m = 0; m < E_DIM; m++) bb += row[m] * out_proj_b[m];
        g_bc[o] = bb;
    }
}

// ---------------- P3: pairwise score tables + v table ------------------------
__device__ __forceinline__ float dot32(const float* a, const float* b) {
    float s = 0.0f;
    #pragma unroll
    for (int d = 0; d < 32; d++) s += a[d] * b[d];
    return s;
}

__global__ void precompute_tables_kernel()
{
    __shared__ float q[E_DIM];
    int ri = blockIdx.x;
    int t = threadIdx.x;

    q[t] = g_tab_qkv[ri * QKV_DIM + t];
    g_vtab[ri * E_DIM + t] = g_tab_qkv[ri * QKV_DIM + 256 + t];
    __syncthreads();

    for (int rj = t; rj < NROWS; rj += 128) {
        const float* k = g_tab_qkv + rj * QKV_DIM + 128;
        float4 s;
        s.x = SCALE * dot32(q + 0,  k + 0);
        s.y = SCALE * dot32(q + 32, k + 32);
        s.z = SCALE * dot32(q + 64, k + 64);
        s.w = SCALE * dot32(q + 96, k + 96);
        g_Spp[ri * NROWS + rj] = s;
    }

    if (t < 4) {
        int h = t;
        ((float*)&g_SqA[ri])[h] = SCALE * dot32(q + 32 * h, g_valA + 128 + 32 * h);
        ((float*)&g_SqB[ri])[h] = SCALE * dot32(q + 32 * h, g_valB + 128 + 32 * h);
    } else if (t < 8) {
        int h = t - 4;
        const float* kr = g_tab_qkv + ri * QKV_DIM + 128 + 32 * h;
        ((float*)&g_SAk[ri])[h] = SCALE * dot32(g_valA + 32 * h, kr);
        ((float*)&g_SBk[ri])[h] = SCALE * dot32(g_valB + 32 * h, kr);
    }

    if (ri == 0 && t >= 8 && t < 12) {
        int h = t - 8;
        const float* Aq = g_valA + 32 * h;
        const float* Bq = g_valB + 32 * h;
        const float* Ak = g_valA + 128 + 32 * h;
        const float* Bk = g_valB + 128 + 32 * h;
        ((float*)&g_c3[0])[h] = SCALE * dot32(Aq, Ak);
        ((float*)&g_c3[1])[h] = SCALE * (dot32(Aq, Bk) + dot32(Bq, Ak));
        ((float*)&g_c3[2])[h] = SCALE * dot32(Bq, Bk);
    }
}

// ---------------- A: attention via tables, one warp per row ------------------
#define SMW 160
#define SC_OFF 0
#define RM_OFF 100
#define RS_OFF 120
#define WK_OFF 140

__global__ void __launch_bounds__(128) attn_kernel(
    const int* __restrict__ dev_ids, const int* __restrict__ pse_ids,
    const int* __restrict__ attr_ids, const int* __restrict__ unit_ids,
    const float* __restrict__ values, const int* __restrict__ mask)
{
    __shared__ float sm[4 * SMW];
    int w = threadIdx.x >> 5;
    int lane = threadIdx.x & 31;
    int n = blockIdx.x * 4 + w;
    float* S = sm + w * SMW;

    int mk0 = mask[n * 5 + 0];
    int mk1 = mask[n * 5 + 1];
    int mk2 = mask[n * 5 + 2];
    int mk3 = mask[n * 5 + 3];
    int mk4 = mask[n * 5 + 4];
    int r0 = mk0 ? dev_ids[n]        : 140;
    int r1 = mk1 ? 10 + pse_ids[n]   : 140;
    int r2 = mk2 ? 20 + attr_ids[n]  : 140;
    int r4 = mk4 ? 120 + unit_ids[n] : 140;
    float val = values[n];

    if (lane < 25) {
        int i = lane / 5;
        int j = lane - i * 5;
        int ri = (i == 0) ? r0 : (i == 1) ? r1 : (i == 2) ? r2 : (i == 3) ? 140 : r4;
        int rj = (j == 0) ? r0 : (j == 1) ? r1 : (j == 2) ? r2 : (j == 3) ? 140 : r4;
        float4 s;
        if (mk3 && (i == 3 || j == 3)) {
            if (i == 3 && j == 3) {
                float4 cAA = g_c3[0], cAB = g_c3[1], cBB = g_c3[2];
                float v2 = val * val;
                s.x = fmaf(v2, cAA.x, fmaf(val, cAB.x, cBB.x));
                s.y = fmaf(v2, cAA.y, fmaf(val, cAB.y, cBB.y));
                s.z = fmaf(v2, cAA.z, fmaf(val, cAB.z, cBB.z));
                s.w = fmaf(v2, cAA.w, fmaf(val, cAB.w, cBB.w));
            } else if (j == 3) {
                float4 a = g_SqA[ri], b = g_SqB[ri];
                s.x = fmaf(val, a.x, b.x);
                s.y = fmaf(val, a.y, b.y);
                s.z = fmaf(val, a.z, b.z);
                s.w = fmaf(val, a.w, b.w);
            } else {
                float4 a = g_SAk[rj], b = g_SBk[rj];
                s.x = fmaf(val, a.x, b.x);
                s.y = fmaf(val, a.y, b.y);
                s.z = fmaf(val, a.z, b.z);
                s.w = fmaf(val, a.w, b.w);
            }
        } else {
            s = g_Spp[ri * NROWS + rj];
        }
        S[SC_OFF + 0 * 25 + lane] = s.x;
        S[SC_OFF + 1 * 25 + lane] = s.y;
        S[SC_OFF + 2 * 25 + lane] = s.z;
        S[SC_OFF + 3 * 25 + lane] = s.w;
    }
    __syncwarp();

    if (lane < 20) {
        int h = lane / 5;
        int i = lane - h * 5;
        const float* sp = S + SC_OFF + h * 25 + i * 5;
        float m = sp[0];
        #pragma unroll
        for (int j = 1; j < 5; j++) m = fmaxf(m, sp[j]);
        float sum = 0.0f;
        #pragma unroll
        for (int j = 0; j < 5; j++) sum += __expf(sp[j] - m);
        S[RM_OFF + lane] = m;
        S[RS_OFF + lane] = 1.0f / sum;
    }
    __syncwarp();

    if (lane < 20) {
        int h = lane / 5;
        int jj = lane - h * 5;
        float acc = 0.0f;
        #pragma unroll
        for (int i = 0; i < 5; i++)
            acc += __expf(S[SC_OFF + h * 25 + i * 5 + jj] - S[RM_OFF + h * 5 + i]) * S[RS_OFF + h * 5 + i];
        S[WK_OFF + lane] = acc * 0.2f;
    }
    __syncwarp();

    const float* v0 = g_vtab + r0 * E_DIM;
    const float* v1 = g_vtab + r1 * E_DIM;
    const float* v2 = g_vtab + r2 * E_DIM;
    const float* v4 = g_vtab + r4 * E_DIM;
    const float* vb = g_vtab + 140 * E_DIM;

    #pragma unroll
    for (int hh = 0; hh < 4; hh++) {
        int e = hh * 32 + lane;
        float wk0 = S[WK_OFF + hh * 5 + 0];
        float wk1 = S[WK_OFF + hh * 5 + 1];
        float wk2 = S[WK_OFF + hh * 5 + 2];
        float wk3 = S[WK_OFF + hh * 5 + 3];
        float wk4 = S[WK_OFF + hh * 5 + 4];
        float v3e = mk3 ? fmaf(val, g_valA[256 + e], g_valB[256 + e]) : vb[e];
        float c = wk0 * v0[e] + wk1 * v1[e] + wk2 * v2[e] + wk3 * v3e + wk4 * v4[e];
        __nv_bfloat16 hi = __float2bfloat16(c);
        g_Ahi[(size_t)n * E_DIM + e] = hi;
        g_Alo[(size_t)n * E_DIM + e] = __float2bfloat16(c - __bfloat162float(hi));
    }
}

// ---------------- G: mma.sync bf16 split GEMM, 256m x 128n, 512 thr ----------
#define GP 136
#define A_ELEMS (256 * GP)
#define B_ELEMS (128 * GP)
#define G_SMEM_BYTES ((2 * A_ELEMS + 2 * B_ELEMS) * 2)   // 208896 B

template <int ROWS>
__device__ __forceinline__ void cp_tile(uint32_t dst_base,
                                        const __nv_bfloat16* __restrict__ src, int tid) {
    #pragma unroll
    for (int it = 0; it < ROWS / 32; it++) {
        int idx = it * 512 + tid;
        int row = idx >> 4;
        int c8 = (idx & 15) << 3;
        cp16(dst_base + (row * GP + c8) * 2, src + row * E_DIM + c8);
    }
}

__global__ void __launch_bounds__(512, 1) gemm_mma_kernel(float* __restrict__ out)
{
    extern __shared__ __nv_bfloat16 smem[];
    __nv_bfloat16* sAhi = smem;
    __nv_bfloat16* sAlo = smem + A_ELEMS;
    __nv_bfloat16* sBhi = smem + 2 * A_ELEMS;
    __nv_bfloat16* sBlo = smem + 2 * A_ELEMS + B_ELEMS;

    const int tid = threadIdx.x;
    const int wid = tid >> 5;
    const int lane = tid & 31;
    const int n0 = blockIdx.x * 128;
    const int m0 = blockIdx.y * 256;

    const uint32_t aHiB = smem_u32(sAhi), aLoB = smem_u32(sAlo);
    const uint32_t bHiB = smem_u32(sBhi), bLoB = smem_u32(sBlo);

    // group 0: hi tiles;  group 1: lo tiles
    cp_tile<256>(aHiB, g_Ahi + (size_t)m0 * E_DIM, tid);
    cp_tile<128>(bHiB, g_Bhi + (size_t)n0 * E_DIM, tid);
    cp_commit();
    cp_tile<256>(aLoB, g_Alo + (size_t)m0 * E_DIM, tid);
    cp_tile<128>(bLoB, g_Blo + (size_t)n0 * E_DIM, tid);
    cp_commit();

    const int wm = (wid & 3) * 64;     // 4 m-groups of 64
    const int wn = (wid >> 2) * 32;    // 4 n-groups of 32

    const uint32_t aLane = ((wm + (lane & 15)) * GP + ((lane >> 4) << 3)) * 2;
    const uint32_t bLane = ((wn + (lane & 7) + ((lane & 16) >> 1)) * GP + (lane & 8)) * 2;

    float c[4][4][4];
    #pragma unroll
    for (int mi = 0; mi < 4; mi++)
        #pragma unroll
        for (int ni = 0; ni < 4; ni++)
            #pragma unroll
            for (int q = 0; q < 4; q++) c[mi][ni][q] = 0.0f;

    cp_wait<1>();
    __syncthreads();

    // pass 0: Ahi * Bhi
    #pragma unroll
    for (int ks = 0; ks < 8; ks++) {
        const uint32_t kOff = (uint32_t)(ks * 16 * 2);
        uint32_t a[4][4];
        #pragma unroll
        for (int mi = 0; mi < 4; mi++)
            ldsm4(a[mi][0], a[mi][1], a[mi][2], a[mi][3],
                  aHiB + aLane + kOff + mi * (16 * GP * 2));
        uint32_t b[4][2];
        #pragma unroll
        for (int bj = 0; bj < 2; bj++)
            ldsm4(b[2 * bj][0], b[2 * bj][1], b[2 * bj + 1][0], b[2 * bj + 1][1],
                  bHiB + bLane + kOff + bj * (16 * GP * 2));
        #pragma unroll
        for (int mi = 0; mi < 4; mi++)
            #pragma unroll
            for (int ni = 0; ni < 4; ni++)
                mma16816(c[mi][ni], a[mi], b[ni]);
    }

    cp_wait<0>();
    __syncthreads();

    // pass 1: Alo * Bhi ; pass 2: Ahi * Blo
    const uint32_t aB2[2] = {aLoB, aHiB};
    const uint32_t bB2[2] = {bHiB, bLoB};
    #pragma unroll 1
    for (int p = 0; p < 2; p++) {
        const uint32_t aBase = aB2[p] + aLane;
        const uint32_t bBase = bB2[p] + bLane;
        #pragma unroll
        for (int ks = 0; ks < 8; ks++) {
            const uint32_t kOff = (uint32_t)(ks * 16 * 2);
            uint32_t a[4][4];
            #pragma unroll
            for (int mi = 0; mi < 4; mi++)
                ldsm4(a[mi][0], a[mi][1], a[mi][2], a[mi][3],
                      aBase + kOff + mi * (16 * GP * 2));
            uint32_t b[4][2];
            #pragma unroll
            for (int bj = 0; bj < 2; bj++)
                ldsm4(b[2 * bj][0], b[2 * bj][1], b[2 * bj + 1][0], b[2 * bj + 1][1],
                      bBase + kOff + bj * (16 * GP * 2));
            #pragma unroll
            for (int mi = 0; mi < 4; mi++)
                #pragma unroll
                for (int ni = 0; ni < 4; ni++)
                    mma16816(c[mi][ni], a[mi], b[ni]);
        }
    }

    // epilogue
    const int mg = m0 + wm + (lane >> 2);
    const int ngb = n0 + wn + 2 * (lane & 3);
    #pragma unroll
    for (int ni = 0; ni < 4; ni++) {
        int col = ngb + ni * 8;
        float2 bc2 = *(const float2*)(g_bc + col);
        #pragma unroll
        for (int mi = 0; mi < 4; mi++) {
            int r0 = mg + mi * 16;
            float2 v0 = {c[mi][ni][0] + bc2.x, c[mi][ni][1] + bc2.y};
            float2 v1 = {c[mi][ni][2] + bc2.x, c[mi][ni][3] + bc2.y};
            *(float2*)(out + (size_t)r0 * OUT_DIM + col) = v0;
            *(float2*)(out + (size_t)(r0 + 8) * OUT_DIM + col) = v1;
        }
    }
}

// ---------------- launch -----------------------------------------------------
extern "C" void kernel_launch(void* const* d_in, const int* in_sizes, int n_in,
                              void* d_out, int out_size)
{
    const int*   device_ids = (const int*)d_in[0];
    const int*   pseudo_ids = (const int*)d_in[1];
    const int*   attr_ids   = (const int*)d_in[2];
    const int*   unit_ids   = (const int*)d_in[3];
    const float* values     = (const float*)d_in[4];
    const int*   mask       = (const int*)d_in[5];
    const float* dev_table  = (const float*)d_in[6];
    const float* pse_table  = (const float*)d_in[7];
    const float* attr_table = (const float*)d_in[8];
    const float* unit_table = (const float*)d_in[9];
    const float* val_w      = (const float*)d_in[10];
    const float* val_b      = (const float*)d_in[11];
    const float* in_proj_w  = (const float*)d_in[12];
    const float* in_proj_b  = (const float*)d_in[13];
    const float* out_proj_w = (const float*)d_in[14];
    const float* out_proj_b = (const float*)d_in[15];
    const float* out_w      = (const float*)d_in[16];
    const float* out_b      = (const float*)d_in[17];
    float* out = (float*)d_out;

    precompute_qkv_kernel<<<143, 384>>>(dev_table, pse_table, attr_table, unit_table,
                                        val_w, val_b, in_proj_w, in_proj_b);
    precompute_wc_kernel<<<768, 128>>>(out_w, out_proj_w, out_proj_b, out_b);
    precompute_tables_kernel<<<NROWS, 128>>>();

    attn_kernel<<<N_TOT / 4, 128>>>(device_ids, pseudo_ids, attr_ids, unit_ids,
                                    values, mask);

    cudaFuncSetAttribute(gemm_mma_kernel, cudaFuncAttributeMaxDynamicSharedMemorySize,
                         G_SMEM_BYTES);
    gemm_mma_kernel<<<dim3(OUT_DIM / 128, N_TOT / 256), 512, G_SMEM_BYTES>>>(out);
}

// round 6
// speedup vs baseline: 4.9469x; 1.6012x over previous
#include <cuda_runtime.h>
#include <cuda_bf16.h>
#include <cuda_fp16.h>
#include <cstdint>

#define N_TOT   131072
#define E_DIM   128
#define QKV_DIM 384
#define OUT_DIM 768
#define NROWS   141   // 140 table rows + bias row (masked token)

// ---------------- device scratch ---------------------------------------------
__device__ float g_tab_qkv[NROWS * QKV_DIM];
__device__ float g_valA[QKV_DIM];
__device__ float g_valB[QKV_DIM];
__device__ float g_bc[OUT_DIM];
__device__ float4 g_Spp[NROWS * NROWS];   // [ri*141+rj] -> 4 head scores (pre-scaled)
__device__ float4 g_SqA[NROWS];
__device__ float4 g_SqB[NROWS];
__device__ float4 g_SAk[NROWS];
__device__ float4 g_SBk[NROWS];
__device__ float4 g_c3[3];                // cAA, cAB, cBB
__device__ float g_vtab[NROWS * E_DIM];
__device__ __half g_Af[(size_t)N_TOT * E_DIM];
__device__ __half g_Bf[OUT_DIM * E_DIM];

#define SCALE 0.17677669529663687f  // 1/sqrt(32)

// ---------------- helpers ----------------------------------------------------
__device__ __forceinline__ uint32_t smem_u32(const void* p) {
    uint32_t a;
    asm("{ .reg .u64 t; cvta.to.shared.u64 t, %1; cvt.u32.u64 %0, t; }" : "=r"(a) : "l"(p));
    return a;
}
__device__ __forceinline__ void ldsm4(uint32_t& r0, uint32_t& r1, uint32_t& r2, uint32_t& r3,
                                      uint32_t addr) {
    asm volatile("ldmatrix.sync.aligned.m8n8.x4.shared.b16 {%0,%1,%2,%3}, [%4];"
                 : "=r"(r0), "=r"(r1), "=r"(r2), "=r"(r3) : "r"(addr));
}
__device__ __forceinline__ void mma16816(float* c, const uint32_t* a, const uint32_t* b) {
    asm volatile(
        "mma.sync.aligned.m16n8k16.row.col.f32.f16.f16.f32 "
        "{%0,%1,%2,%3}, {%4,%5,%6,%7}, {%8,%9}, {%0,%1,%2,%3};"
        : "+f"(c[0]), "+f"(c[1]), "+f"(c[2]), "+f"(c[3])
        : "r"(a[0]), "r"(a[1]), "r"(a[2]), "r"(a[3]), "r"(b[0]), "r"(b[1]));
}
__device__ __forceinline__ void cp16(uint32_t dst, const void* src) {
    asm volatile("cp.async.cg.shared.global [%0], [%1], 16;" :: "r"(dst), "l"(src));
}
__device__ __forceinline__ void cp_commit() {
    asm volatile("cp.async.commit_group;" ::: "memory");
}
template <int N>
__device__ __forceinline__ void cp_wait() {
    asm volatile("cp.async.wait_group %0;" :: "n"(N) : "memory");
}

// ---------------- P1: qkv rows for tables + bias row + valA/valB -------------
__global__ void precompute_qkv_kernel(
    const float* __restrict__ dev_t, const float* __restrict__ pse_t,
    const float* __restrict__ attr_t, const float* __restrict__ unit_t,
    const float* __restrict__ val_w, const float* __restrict__ val_b,
    const float* __restrict__ W, const float* __restrict__ b)
{
    __shared__ float emb[E_DIM];
    int blk = blockIdx.x;
    int j = threadIdx.x;

    const float* src = nullptr;
    float* dst;
    int has_bias = 1;
    if (blk < 10)        { src = dev_t  + blk * E_DIM;         dst = g_tab_qkv + blk * QKV_DIM; }
    else if (blk < 20)   { src = pse_t  + (blk - 10) * E_DIM;  dst = g_tab_qkv + blk * QKV_DIM; }
    else if (blk < 120)  { src = attr_t + (blk - 20) * E_DIM;  dst = g_tab_qkv + blk * QKV_DIM; }
    else if (blk < 140)  { src = unit_t + (blk - 120) * E_DIM; dst = g_tab_qkv + blk * QKV_DIM; }
    else if (blk == 140) { src = nullptr; dst = g_tab_qkv + 140 * QKV_DIM; }
    else if (blk == 141) { src = val_w; dst = g_valA; has_bias = 0; }
    else                 { src = val_b; dst = g_valB; }

    if (j < E_DIM) emb[j] = src ? src[j] : 0.0f;
    __syncthreads();

    const float4* Wr = (const float4*)(W + (size_t)j * E_DIM);
    const float4* em = (const float4*)emb;
    float acc = has_bias ? b[j] : 0.0f;
    #pragma unroll
    for (int e4 = 0; e4 < E_DIM / 4; e4++) {
        float4 w = Wr[e4];
        float4 v = em[e4];
        acc += w.x * v.x + w.y * v.y + w.z * v.z + w.w * v.w;
    }
    dst[j] = acc;
}

// ---------------- P2: Wc = out_w @ out_proj_w  (fp16) ------------------------
__global__ void precompute_wc_kernel(
    const float* __restrict__ out_w, const float* __restrict__ out_proj_w,
    const float* __restrict__ out_proj_b, const float* __restrict__ out_b)
{
    __shared__ float row[E_DIM];
    int o = blockIdx.x;
    int e = threadIdx.x;
    row[e] = out_w[(size_t)o * E_DIM + e];
    __syncthreads();

    float acc = 0.0f;
    #pragma unroll 8
    for (int m = 0; m < E_DIM; m++)
        acc += row[m] * out_proj_w[(size_t)m * E_DIM + e];

    g_Bf[(size_t)o * E_DIM + e] = __float2half(acc);

    if (e == 0) {
        float bb = out_b[o];
        for (int m = 0; m < E_DIM; m++) bb += row[m] * out_proj_b[m];
        g_bc[o] = bb;
    }
}

// ---------------- P3: pairwise score tables + v table ------------------------
__device__ __forceinline__ float dot32(const float* a, const float* b) {
    float s = 0.0f;
    #pragma unroll
    for (int d = 0; d < 32; d++) s += a[d] * b[d];
    return s;
}

__global__ void precompute_tables_kernel()
{
    __shared__ float q[E_DIM];
    int ri = blockIdx.x;
    int t = threadIdx.x;

    q[t] = g_tab_qkv[ri * QKV_DIM + t];
    g_vtab[ri * E_DIM + t] = g_tab_qkv[ri * QKV_DIM + 256 + t];
    __syncthreads();

    for (int rj = t; rj < NROWS; rj += 128) {
        const float* k = g_tab_qkv + rj * QKV_DIM + 128;
        float4 s;
        s.x = SCALE * dot32(q + 0,  k + 0);
        s.y = SCALE * dot32(q + 32, k + 32);
        s.z = SCALE * dot32(q + 64, k + 64);
        s.w = SCALE * dot32(q + 96, k + 96);
        g_Spp[ri * NROWS + rj] = s;
    }

    if (t < 4) {
        int h = t;
        ((float*)&g_SqA[ri])[h] = SCALE * dot32(q + 32 * h, g_valA + 128 + 32 * h);
        ((float*)&g_SqB[ri])[h] = SCALE * dot32(q + 32 * h, g_valB + 128 + 32 * h);
    } else if (t < 8) {
        int h = t - 4;
        const float* kr = g_tab_qkv + ri * QKV_DIM + 128 + 32 * h;
        ((float*)&g_SAk[ri])[h] = SCALE * dot32(g_valA + 32 * h, kr);
        ((float*)&g_SBk[ri])[h] = SCALE * dot32(g_valB + 32 * h, kr);
    }

    if (ri == 0 && t >= 8 && t < 12) {
        int h = t - 8;
        const float* Aq = g_valA + 32 * h;
        const float* Bq = g_valB + 32 * h;
        const float* Ak = g_valA + 128 + 32 * h;
        const float* Bk = g_valB + 128 + 32 * h;
        ((float*)&g_c3[0])[h] = SCALE * dot32(Aq, Ak);
        ((float*)&g_c3[1])[h] = SCALE * (dot32(Aq, Bk) + dot32(Bq, Ak));
        ((float*)&g_c3[2])[h] = SCALE * dot32(Bq, Bk);
    }
}

// ---------------- A: attention via tables, one warp per row ------------------
#define SMW 160
#define SC_OFF 0
#define RM_OFF 100
#define RS_OFF 120
#define WK_OFF 140

__global__ void __launch_bounds__(128) attn_kernel(
    const int* __restrict__ dev_ids, const int* __restrict__ pse_ids,
    const int* __restrict__ attr_ids, const int* __restrict__ unit_ids,
    const float* __restrict__ values, const int* __restrict__ mask)
{
    __shared__ float sm[4 * SMW];
    int w = threadIdx.x >> 5;
    int lane = threadIdx.x & 31;
    int n = blockIdx.x * 4 + w;
    float* S = sm + w * SMW;

    int mk0 = mask[n * 5 + 0];
    int mk1 = mask[n * 5 + 1];
    int mk2 = mask[n * 5 + 2];
    int mk3 = mask[n * 5 + 3];
    int mk4 = mask[n * 5 + 4];
    int r0 = mk0 ? dev_ids[n]        : 140;
    int r1 = mk1 ? 10 + pse_ids[n]   : 140;
    int r2 = mk2 ? 20 + attr_ids[n]  : 140;
    int r4 = mk4 ? 120 + unit_ids[n] : 140;
    float val = values[n];

    if (lane < 25) {
        int i = lane / 5;
        int j = lane - i * 5;
        int ri = (i == 0) ? r0 : (i == 1) ? r1 : (i == 2) ? r2 : (i == 3) ? 140 : r4;
        int rj = (j == 0) ? r0 : (j == 1) ? r1 : (j == 2) ? r2 : (j == 3) ? 140 : r4;
        float4 s;
        if (mk3 && (i == 3 || j == 3)) {
            if (i == 3 && j == 3) {
                float4 cAA = g_c3[0], cAB = g_c3[1], cBB = g_c3[2];
                float v2 = val * val;
                s.x = fmaf(v2, cAA.x, fmaf(val, cAB.x, cBB.x));
                s.y = fmaf(v2, cAA.y, fmaf(val, cAB.y, cBB.y));
                s.z = fmaf(v2, cAA.z, fmaf(val, cAB.z, cBB.z));
                s.w = fmaf(v2, cAA.w, fmaf(val, cAB.w, cBB.w));
            } else if (j == 3) {
                float4 a = g_SqA[ri], b = g_SqB[ri];
                s.x = fmaf(val, a.x, b.x);
                s.y = fmaf(val, a.y, b.y);
                s.z = fmaf(val, a.z, b.z);
                s.w = fmaf(val, a.w, b.w);
            } else {
                float4 a = g_SAk[rj], b = g_SBk[rj];
                s.x = fmaf(val, a.x, b.x);
                s.y = fmaf(val, a.y, b.y);
                s.z = fmaf(val, a.z, b.z);
                s.w = fmaf(val, a.w, b.w);
            }
        } else {
            s = g_Spp[ri * NROWS + rj];
        }
        S[SC_OFF + 0 * 25 + lane] = s.x;
        S[SC_OFF + 1 * 25 + lane] = s.y;
        S[SC_OFF + 2 * 25 + lane] = s.z;
        S[SC_OFF + 3 * 25 + lane] = s.w;
    }
    __syncwarp();

    if (lane < 20) {
        int h = lane / 5;
        int i = lane - h * 5;
        const float* sp = S + SC_OFF + h * 25 + i * 5;
        float m = sp[0];
        #pragma unroll
        for (int j = 1; j < 5; j++) m = fmaxf(m, sp[j]);
        float sum = 0.0f;
        #pragma unroll
        for (int j = 0; j < 5; j++) sum += __expf(sp[j] - m);
        S[RM_OFF + lane] = m;
        S[RS_OFF + lane] = 1.0f / sum;
    }
    __syncwarp();

    if (lane < 20) {
        int h = lane / 5;
        int jj = lane - h * 5;
        float acc = 0.0f;
        #pragma unroll
        for (int i = 0; i < 5; i++)
            acc += __expf(S[SC_OFF + h * 25 + i * 5 + jj] - S[RM_OFF + h * 5 + i]) * S[RS_OFF + h * 5 + i];
        S[WK_OFF + lane] = acc * 0.2f;
    }
    __syncwarp();

    const float* v0 = g_vtab + r0 * E_DIM;
    const float* v1 = g_vtab + r1 * E_DIM;
    const float* v2 = g_vtab + r2 * E_DIM;
    const float* v4 = g_vtab + r4 * E_DIM;
    const float* vb = g_vtab + 140 * E_DIM;

    #pragma unroll
    for (int hh = 0; hh < 4; hh++) {
        int e = hh * 32 + lane;
        float wk0 = S[WK_OFF + hh * 5 + 0];
        float wk1 = S[WK_OFF + hh * 5 + 1];
        float wk2 = S[WK_OFF + hh * 5 + 2];
        float wk3 = S[WK_OFF + hh * 5 + 3];
        float wk4 = S[WK_OFF + hh * 5 + 4];
        float v3e = mk3 ? fmaf(val, g_valA[256 + e], g_valB[256 + e]) : vb[e];
        float c = wk0 * v0[e] + wk1 * v1[e] + wk2 * v2[e] + wk3 * v3e + wk4 * v4[e];
        g_Af[(size_t)n * E_DIM + e] = __float2half(c);
    }
}

// ---------------- G: mma.sync fp16 single-pass GEMM --------------------------
// 128m x 128n per CTA, 256 threads, 2 CTAs/SM. warp tile 64m x 32n.
#define GP 136
#define A_ELEMS (128 * GP)
#define B_ELEMS (128 * GP)
#define G_SMEM_BYTES ((A_ELEMS + B_ELEMS) * 2)   // 69632 B

template <int ROWS>
__device__ __forceinline__ void cp_tile(uint32_t dst_base,
                                        const __half* __restrict__ src, int tid) {
    #pragma unroll
    for (int it = 0; it < ROWS / 16; it++) {
        int idx = it * 256 + tid;
        int row = idx >> 4;
        int c8 = (idx & 15) << 3;
        cp16(dst_base + (row * GP + c8) * 2, src + row * E_DIM + c8);
    }
}

__global__ void __launch_bounds__(256, 2) gemm_mma_kernel(float* __restrict__ out)
{
    extern __shared__ __half smem[];
    __half* sA = smem;
    __half* sB = smem + A_ELEMS;

    const int tid = threadIdx.x;
    const int wid = tid >> 5;
    const int lane = tid & 31;
    const int n0 = blockIdx.x * 128;
    const int m0 = blockIdx.y * 128;

    const uint32_t aB = smem_u32(sA);
    const uint32_t bBv = smem_u32(sB);

    cp_tile<128>(aB, g_Af + (size_t)m0 * E_DIM, tid);
    cp_tile<128>(bBv, g_Bf + (size_t)n0 * E_DIM, tid);
    cp_commit();

    const int wm = (wid & 1) * 64;     // 2 m-groups of 64
    const int wn = (wid >> 1) * 32;    // 4 n-groups of 32

    const uint32_t aLane = aB + ((wm + (lane & 15)) * GP + ((lane >> 4) << 3)) * 2;
    const uint32_t bLane = bBv + ((wn + (lane & 7) + ((lane & 16) >> 1)) * GP + (lane & 8)) * 2;

    float c[4][4][4];
    #pragma unroll
    for (int mi = 0; mi < 4; mi++)
        #pragma unroll
        for (int ni = 0; ni < 4; ni++)
            #pragma unroll
            for (int q = 0; q < 4; q++) c[mi][ni][q] = 0.0f;

    cp_wait<0>();
    __syncthreads();

    #pragma unroll
    for (int ks = 0; ks < 8; ks++) {
        const uint32_t kOff = (uint32_t)(ks * 16 * 2);
        uint32_t a[4][4];
        #pragma unroll
        for (int mi = 0; mi < 4; mi++)
            ldsm4(a[mi][0], a[mi][1], a[mi][2], a[mi][3],
                  aLane + kOff + mi * (16 * GP * 2));
        uint32_t b[4][2];
        #pragma unroll
        for (int bj = 0; bj < 2; bj++)
            ldsm4(b[2 * bj][0], b[2 * bj][1], b[2 * bj + 1][0], b[2 * bj + 1][1],
                  bLane + kOff + bj * (16 * GP * 2));
        #pragma unroll
        for (int mi = 0; mi < 4; mi++)
            #pragma unroll
            for (int ni = 0; ni < 4; ni++)
                mma16816(c[mi][ni], a[mi], b[ni]);
    }

    // epilogue
    const int mg = m0 + wm + (lane >> 2);
    const int ngb = n0 + wn + 2 * (lane & 3);
    #pragma unroll
    for (int ni = 0; ni < 4; ni++) {
        int col = ngb + ni * 8;
        float2 bc2 = *(const float2*)(g_bc + col);
        #pragma unroll
        for (int mi = 0; mi < 4; mi++) {
            int r0 = mg + mi * 16;
            float2 v0 = {c[mi][ni][0] + bc2.x, c[mi][ni][1] + bc2.y};
            float2 v1 = {c[mi][ni][2] + bc2.x, c[mi][ni][3] + bc2.y};
            *(float2*)(out + (size_t)r0 * OUT_DIM + col) = v0;
            *(float2*)(out + (size_t)(r0 + 8) * OUT_DIM + col) = v1;
        }
    }
}

// ---------------- launch -----------------------------------------------------
extern "C" void kernel_launch(void* const* d_in, const int* in_sizes, int n_in,
                              void* d_out, int out_size)
{
    const int*   device_ids = (const int*)d_in[0];
    const int*   pseudo_ids = (const int*)d_in[1];
    const int*   attr_ids   = (const int*)d_in[2];
    const int*   unit_ids   = (const int*)d_in[3];
    const float* values     = (const float*)d_in[4];
    const int*   mask       = (const int*)d_in[5];
    const float* dev_table  = (const float*)d_in[6];
    const float* pse_table  = (const float*)d_in[7];
    const float* attr_table = (const float*)d_in[8];
    const float* unit_table = (const float*)d_in[9];
    const float* val_w      = (const float*)d_in[10];
    const float* val_b      = (const float*)d_in[11];
    const float* in_proj_w  = (const float*)d_in[12];
    const float* in_proj_b  = (const float*)d_in[13];
    const float* out_proj_w = (const float*)d_in[14];
    const float* out_proj_b = (const float*)d_in[15];
    const float* out_w      = (const float*)d_in[16];
    const float* out_b      = (const float*)d_in[17];
    float* out = (float*)d_out;

    precompute_qkv_kernel<<<143, 384>>>(dev_table, pse_table, attr_table, unit_table,
                                        val_w, val_b, in_proj_w, in_proj_b);
    precompute_wc_kernel<<<768, 128>>>(out_w, out_proj_w, out_proj_b, out_b);
    precompute_tables_kernel<<<NROWS, 128>>>();

    attn_kernel<<<N_TOT / 4, 128>>>(device_ids, pseudo_ids, attr_ids, unit_ids,
                                    values, mask);

    cudaFuncSetAttribute(gemm_mma_kernel, cudaFuncAttributeMaxDynamicSharedMemorySize,
                         G_SMEM_BYTES);
    gemm_mma_kernel<<<dim3(OUT_DIM / 128, N_TOT / 128), 256, G_SMEM_BYTES>>>(out);
}